// round 1
// baseline (speedup 1.0000x reference)
#include <cuda_runtime.h>
#include <cuda_bf16.h>

// Bidirectional linear RNN (units=1, linear activation, no bias):
//   fw_t = sum_{s<=t} r^{t-s} * k * x_s      (h_t = k*x_t + r*h_{t-1}, h_{-1}=0)
//   bw_t = sum_{s>=t} r^{s-t} * k * x_s
// Outputs: out_stateless[B,T,2] (fw,bw interleaved), diff[B,T,2] = 0.
// d_out layout: flat concat [stateless (B*T*2 floats) | diff (B*T*2 floats)].
//
// Exact chunked-scan: per block = one row. 256 threads x 16 elems/thread in
// registers. Chunk transform has uniform multiplier q = r^16, so the seed
// scan is a first-order Kogge-Stone over 256 threads (8 steps, fw+bw fused).

#define BB      4096
#define TT      4096
#define THREADS 256
#define CHUNK   16

__global__ __launch_bounds__(THREADS) void birnn_kernel(
    const float* __restrict__ x,
    const float* __restrict__ kp,
    const float* __restrict__ rp,
    float* __restrict__ out)
{
    // Overlaid buffer:
    //  phase A: x row, pad 1 word per 16  -> needs 4096+256 = 4352 floats
    //  phase B: out staging, pad 1 word per 32 -> needs 8192+256 = 8448 floats
    __shared__ float sbuf[8448];
    __shared__ float Sf[THREADS];
    __shared__ float Sb[THREADS];

    const int b   = blockIdx.x;
    const int tid = threadIdx.x;
    const float k = *kp;
    const float r = *rp;

    // ---- Phase A: coalesced load of this row into padded smem ----
    const float* xrow = x + (size_t)b * TT;
    for (int i = tid; i < TT / 4; i += THREADS) {
        float4 v = ((const float4*)xrow)[i];
        int idx = 4 * i;
        int p = idx + (idx >> 4);          // pad 1 per 16 words
        sbuf[p + 0] = v.x; sbuf[p + 1] = v.y;
        sbuf[p + 2] = v.z; sbuf[p + 3] = v.w;
    }
    __syncthreads();

    // ---- Pull my 16 consecutive elements into registers (conflict-free) ----
    float xv[CHUNK];
    {
        int base = tid * CHUNK;            // multiple of 16 -> whole group
        int p = base + (base >> 4);        // = 17*tid, bank stride 17 (odd)
        #pragma unroll
        for (int j = 0; j < CHUNK; j++) xv[j] = sbuf[p + j];
    }

    // ---- Pass 1: local chunk results from zero state ----
    float bL = 0.f;                        // fw: ascending
    #pragma unroll
    for (int j = 0; j < CHUNK; j++) bL = fmaf(r, bL, k * xv[j]);
    float bR = 0.f;                        // bw: descending
    #pragma unroll
    for (int j = CHUNK - 1; j >= 0; j--) bR = fmaf(r, bR, k * xv[j]);

    Sf[tid] = bL;
    Sb[tid] = bR;

    // q = r^16 (uniform chunk multiplier)
    float q = r * r; q = q * q; q = q * q; q = q * q;

    float vf = bL, vb = bR;
    float qd = q;
    __syncthreads();                       // also fences all sbuf (x) reads

    // ---- Kogge-Stone scan of first-order recurrence, fw + bw fused ----
    #pragma unroll
    for (int d = 1; d < THREADS; d <<= 1) {
        float of = (tid >= d)           ? Sf[tid - d] : 0.f;
        float ob = (tid + d < THREADS)  ? Sb[tid + d] : 0.f;
        __syncthreads();
        vf = fmaf(qd, of, vf);
        vb = fmaf(qd, ob, vb);
        Sf[tid] = vf;
        Sb[tid] = vb;
        qd *= qd;
        __syncthreads();
    }
    const float seedF = (tid > 0)           ? Sf[tid - 1] : 0.f;
    const float seedB = (tid < THREADS - 1) ? Sb[tid + 1] : 0.f;

    // ---- Pass 2: recompute with seeds, stage interleaved (fw,bw) in smem ----
    {
        int obase = tid * 2 * CHUNK;       // 32*tid -> group tid exactly
        int p = obase + (obase >> 5);      // = 33*tid, conflict-free
        float h = seedF;
        #pragma unroll
        for (int j = 0; j < CHUNK; j++) {
            h = fmaf(r, h, k * xv[j]);
            sbuf[p + 2 * j] = h;
        }
        float hb = seedB;
        #pragma unroll
        for (int j = CHUNK - 1; j >= 0; j--) {
            hb = fmaf(r, hb, k * xv[j]);
            sbuf[p + 2 * j + 1] = hb;
        }
    }
    __syncthreads();

    // ---- Coalesced writeback: stateless row + zero diff row ----
    float* orow = out + (size_t)b * (2 * TT);
    float* drow = out + (size_t)BB * TT * 2 + (size_t)b * (2 * TT);
    const float4 z4 = make_float4(0.f, 0.f, 0.f, 0.f);
    for (int m = tid; m < (2 * TT) / 4; m += THREADS) {
        int idx = 4 * m;
        int p = idx + (idx >> 5);          // 4 words stay inside one group
        float4 v = make_float4(sbuf[p], sbuf[p + 1], sbuf[p + 2], sbuf[p + 3]);
        ((float4*)orow)[m] = v;
        ((float4*)drow)[m] = z4;
    }
}

extern "C" void kernel_launch(void* const* d_in, const int* in_sizes, int n_in,
                              void* d_out, int out_size)
{
    const float* x  = (const float*)d_in[0];
    const float* kp = (const float*)d_in[1];
    const float* rp = (const float*)d_in[2];
    float* out = (float*)d_out;
    birnn_kernel<<<BB, THREADS>>>(x, kp, rp, out);
}

// round 2
// speedup vs baseline: 1.0451x; 1.0451x over previous
#include <cuda_runtime.h>
#include <cuda_bf16.h>

// Bidirectional linear RNN (units=1, linear, no bias), B=T=4096, scalar k,r.
//   fw_t = k*x_t + r*fw_{t-1};  bw_t = k*x_t + r*bw_{t+1}
// d_out = [stateless (B*T*2) | diff (B*T*2 zeros)], fw/bw interleaved.
//
// Grid 6144, interleaved 2:1 -> 4096 RNN blocks + 2048 zero-fill blocks.
// RNN block: 256 thr x 16 elems in regs; chunk multiplier q=r^16 uniform, so
// block scan = warp shfl scan (factor q) + 8-aggregate fold (factor q^32).
// Only 3 __syncthreads per RNN block. Zero blocks: pure streaming stcs.

#define BB      4096
#define TT      4096
#define THREADS 256
#define CHUNK   16
#define NWARP   (THREADS / 32)

__global__ __launch_bounds__(THREADS) void birnn_kernel(
    const float* __restrict__ x,
    const float* __restrict__ kp,
    const float* __restrict__ rp,
    float* __restrict__ out)
{
    __shared__ float sbuf[8448];      // x (padded 1/16) then out staging (1/32)
    __shared__ float Af[NWARP];       // fw warp aggregates
    __shared__ float Ab[NWARP];       // bw warp aggregates

    const int z  = blockIdx.x;
    const int m3 = z % 3;
    const int tid = threadIdx.x;

    float* const diffBase = out + (size_t)BB * TT * 2;

    if (m3 == 2) {
        // ---------- pure streaming zero-fill block ----------
        const int seg = z / 3;                      // 0..2047
        float4* dst = (float4*)diffBase + (size_t)seg * 4096;
        const float4 z4 = make_float4(0.f, 0.f, 0.f, 0.f);
        #pragma unroll 4
        for (int m = tid; m < 4096; m += THREADS)
            __stcs(dst + m, z4);
        return;
    }

    // ---------- RNN block ----------
    const int b    = (z / 3) * 2 + m3;              // row 0..4095
    const int lane = tid & 31;
    const int w    = tid >> 5;
    const float k  = *kp;
    const float r  = *rp;

    // q = r^16, Q = q^32 = r^512
    float q = r * r; q = q * q; q = q * q; q = q * q;
    float Q = q;
    #pragma unroll
    for (int i = 0; i < 5; i++) Q = Q * Q;

    // Coalesced load of row into padded smem
    const float4* xrow = (const float4*)(x + (size_t)b * TT);
    #pragma unroll
    for (int i = tid; i < TT / 4; i += THREADS) {
        float4 v = __ldcs(xrow + i);
        int idx = 4 * i;
        int p = idx + (idx >> 4);
        sbuf[p + 0] = v.x; sbuf[p + 1] = v.y;
        sbuf[p + 2] = v.z; sbuf[p + 3] = v.w;
    }
    __syncthreads();                                 // barrier 1

    // My 16 consecutive elements (bank-conflict-free, stride 17)
    float xv[CHUNK];
    {
        int p = tid * 17;                            // 16*tid + tid
        #pragma unroll
        for (int j = 0; j < CHUNK; j++) xv[j] = sbuf[p + j];
    }

    // Local chunk scans from zero state
    float bL = 0.f, bR = 0.f;
    #pragma unroll
    for (int j = 0; j < CHUNK; j++) bL = fmaf(r, bL, k * xv[j]);
    #pragma unroll
    for (int j = CHUNK - 1; j >= 0; j--) bR = fmaf(r, bR, k * xv[j]);

    // Warp-level first-order scans (factor q), fw ascending / bw descending
    float vf = bL, vb = bR, qd = q;
    #pragma unroll
    for (int d = 1; d < 32; d <<= 1) {
        float of = __shfl_up_sync(0xffffffffu, vf, d);
        float ob = __shfl_down_sync(0xffffffffu, vb, d);
        if (lane >= d)     vf = fmaf(qd, of, vf);
        if (lane + d < 32) vb = fmaf(qd, ob, vb);
        qd *= qd;
    }
    if (lane == 31) Af[w] = vf;
    if (lane == 0)  Ab[w] = vb;
    __syncthreads();                                 // barrier 2

    // Fold warp aggregates (factor Q) -> exclusive prefixes, per thread
    float Ef = 0.f;
    #pragma unroll
    for (int u = 0; u < NWARP; u++)
        if (u < w) Ef = fmaf(Q, Ef, Af[u]);
    float Eb = 0.f;
    #pragma unroll
    for (int u = NWARP - 1; u >= 0; u--)
        if (u > w) Eb = fmaf(Q, Eb, Ab[u]);

    // q^lane and q^(31-lane)
    float pwf = 1.f, pwb = 1.f, t = q;
    #pragma unroll
    for (int bit = 0; bit < 5; bit++) {
        if (lane & (1 << bit))        pwf *= t;
        if ((31 - lane) & (1 << bit)) pwb *= t;
        t *= t;
    }

    float hfp = __shfl_up_sync(0xffffffffu, vf, 1);   // h_{c-1}
    float hbn = __shfl_down_sync(0xffffffffu, vb, 1); // h'_{c+1}
    const float seedF = (lane > 0)  ? fmaf(pwf, Ef, hfp) : Ef;
    const float seedB = (lane < 31) ? fmaf(pwb, Eb, hbn) : Eb;

    // Recompute with seeds, stage interleaved (fw,bw) pairs (stride 33)
    {
        int p = tid * 33;                             // 32*tid + tid
        float h = seedF;
        #pragma unroll
        for (int j = 0; j < CHUNK; j++) {
            h = fmaf(r, h, k * xv[j]);
            sbuf[p + 2 * j] = h;
        }
        float hb = seedB;
        #pragma unroll
        for (int j = CHUNK - 1; j >= 0; j--) {
            hb = fmaf(r, hb, k * xv[j]);
            sbuf[p + 2 * j + 1] = hb;
        }
    }
    __syncthreads();                                 // barrier 3

    // Coalesced streaming writeback of the stateless row
    float4* orow = (float4*)(out + (size_t)b * (2 * TT));
    #pragma unroll
    for (int m = tid; m < (2 * TT) / 4; m += THREADS) {
        int idx = 4 * m;
        int p = idx + (idx >> 5);
        float4 v = make_float4(sbuf[p], sbuf[p + 1], sbuf[p + 2], sbuf[p + 3]);
        __stcs(orow + m, v);
    }
}

extern "C" void kernel_launch(void* const* d_in, const int* in_sizes, int n_in,
                              void* d_out, int out_size)
{
    const float* x  = (const float*)d_in[0];
    const float* kp = (const float*)d_in[1];
    const float* rp = (const float*)d_in[2];
    float* out = (float*)d_out;
    birnn_kernel<<<BB + BB / 2, THREADS>>>(x, kp, rp, out);
}